// round 1
// baseline (speedup 1.0000x reference)
#include <cuda_runtime.h>

#define NN   50000
#define KK   25
#define FF   128
#define TT   256
#define OUTD 128
#define NBLK 148
#define NKTOT 1250000
#define EPSB 1e-3f

typedef unsigned long long u64;

// ---------------- scratch (static __device__, no allocs) ----------------
__device__ float  d_maxZ[(size_t)NN * TT];
__device__ float  d_minZ[(size_t)NN * TT];
__device__ float  d_SW[(size_t)NN * OUTD];
__device__ float  d_PW[(size_t)NN * OUTD];
__device__ double d_pBs[NBLK * TT];
__device__ double d_pBq[NBLK * TT];
__device__ float  d_pC1s[NBLK * 256];
__device__ float  d_pC1q[NBLK * 256];
__device__ float  d_pC2s[NBLK * 128];
__device__ float  d_pC2q[NBLK * 128];
__device__ float  d_a1[TT], d_c1[TT];
__device__ float  d_a2[256], d_c2[256];

// ---------------- packed fp32x2 helpers (sm_103a) ----------------
__device__ __forceinline__ u64 pack2(float lo, float hi) {
    u64 r;
    asm("mov.b64 %0, {%1, %2};" : "=l"(r) : "f"(lo), "f"(hi));
    return r;
}
__device__ __forceinline__ void fma2(u64& acc, u64 a, u64 b) {
    asm("fma.rn.f32x2 %0, %1, %2, %0;" : "+l"(acc) : "l"(a), "l"(b));
}
__device__ __forceinline__ float2 unpack2(u64 v) {
    float lo, hi;
    asm("mov.b64 {%0, %1}, %2;" : "=f"(lo), "=f"(hi) : "l"(v));
    return make_float2(lo, hi);
}

// ---------------- pass B: z = neigh @ Wt ; per-node col max/min ; Σz, Σz² ----------------
// 256 threads, thread t owns column t. Wt column in 64 f32x2 regs (persistent).
__global__ void __launch_bounds__(256, 1)
passB(const float* __restrict__ neigh, const float* __restrict__ Wt) {
    __shared__ float4 xs4[KK * FF / 4];   // 25x128 floats = 12.8 KB
    const int t = threadIdx.x;

    u64 w2[FF / 2];
#pragma unroll
    for (int i = 0; i < FF / 2; ++i)
        w2[i] = pack2(Wt[(2 * i) * TT + t], Wt[(2 * i + 1) * TT + t]);

    double szd = 0.0, sqd = 0.0;

    for (int n = blockIdx.x; n < NN; n += gridDim.x) {
        __syncthreads();
        const float4* src = (const float4*)(neigh + (size_t)n * (KK * FF));
        for (int i = t; i < KK * FF / 4; i += 256) xs4[i] = src[i];
        __syncthreads();

        float zmax = -3.4e38f, zmin = 3.4e38f, ns = 0.f, nq = 0.f;
#pragma unroll 1
        for (int k = 0; k < KK; ++k) {
            const ulonglong2* xr = ((const ulonglong2*)xs4) + k * (FF / 4);
            u64 acc0 = 0ull, acc1 = 0ull;
#pragma unroll
            for (int i = 0; i < FF / 4; ++i) {
                ulonglong2 xv = xr[i];
                fma2(acc0, xv.x, w2[2 * i]);
                fma2(acc1, xv.y, w2[2 * i + 1]);
            }
            float2 fa = unpack2(acc0), fb = unpack2(acc1);
            float z = (fa.x + fa.y) + (fb.x + fb.y);
            zmax = fmaxf(zmax, z);
            zmin = fminf(zmin, z);
            ns += z;
            nq = fmaf(z, z, nq);
        }
        d_maxZ[(size_t)n * TT + t] = zmax;
        d_minZ[(size_t)n * TT + t] = zmin;
        szd += (double)ns;
        sqd += (double)nq;
    }
    d_pBs[blockIdx.x * TT + t] = szd;
    d_pBq[blockIdx.x * TT + t] = sqd;
}

// ---------------- stats1: BN1 affine a1,c1 (bt cancels inside BN) ----------------
__global__ void stats1(const float* __restrict__ g1, const float* __restrict__ b1) {
    const int t = threadIdx.x;  // 256
    double s = 0.0, q = 0.0;
    for (int b = 0; b < NBLK; ++b) { s += d_pBs[b * TT + t]; q += d_pBq[b * TT + t]; }
    const double inv = 1.0 / (double)NKTOT;
    const double m = s * inv;
    const double var = q * inv - m * m;
    const float a = g1[t] * rsqrtf((float)var + EPSB);
    d_a1[t] = a;
    d_c1[t] = b1[t] - a * (float)m;
}

// ---------------- pass C1: SW = self @ Ws ; column Σ, Σ² ----------------
// 256 threads process 2 nodes per iter: which = tid>>7, j = tid&127.
__global__ void __launch_bounds__(256, 1)
passC1(const float* __restrict__ selfn, const float* __restrict__ Ws) {
    __shared__ float4 xs4[2 * FF / 4];  // 2 rows x 128
    float* xs = (float*)xs4;
    const int tid = threadIdx.x;
    const int which = tid >> 7;
    const int j = tid & 127;

    u64 w2[FF / 2];
#pragma unroll
    for (int i = 0; i < FF / 2; ++i)
        w2[i] = pack2(Ws[(2 * i) * OUTD + j], Ws[(2 * i + 1) * OUTD + j]);

    float s = 0.f, q = 0.f;
    for (int base = blockIdx.x * 2; base < NN; base += gridDim.x * 2) {
        __syncthreads();
        xs[tid] = selfn[(size_t)base * FF + tid];
        __syncthreads();
        const ulonglong2* xr = (const ulonglong2*)(xs + which * FF);
        u64 acc0 = 0ull, acc1 = 0ull;
#pragma unroll
        for (int i = 0; i < FF / 4; ++i) {
            ulonglong2 xv = xr[i];
            fma2(acc0, xv.x, w2[2 * i]);
            fma2(acc1, xv.y, w2[2 * i + 1]);
        }
        float2 fa = unpack2(acc0), fb = unpack2(acc1);
        float z = (fa.x + fa.y) + (fb.x + fb.y);
        d_SW[(size_t)(base + which) * OUTD + j] = z;
        s += z;
        q = fmaf(z, z, q);
    }
    d_pC1s[blockIdx.x * 256 + tid] = s;
    d_pC1q[blockIdx.x * 256 + tid] = q;
}

// ---------------- pass C2: pooled = a1*max/min + c1 ; PW = pooled @ Wn ; Σ, Σ² ----------------
// thread = (half = tid>>7, j = tid&127): half of the T range for output col j.
__global__ void __launch_bounds__(256, 1)
passC2(const float* __restrict__ Wn) {
    __shared__ float4 pos4[TT / 4];
    __shared__ float4 sred4[256 / 4];
    float* pos = (float*)pos4;
    float* sred = (float*)sred4;
    const int tid = threadIdx.x;
    const int half = tid >> 7;
    const int j = tid & 127;

    u64 w2[FF / 2];
#pragma unroll
    for (int i = 0; i < FF / 2; ++i) {
        int t0 = half * 128 + 2 * i;
        w2[i] = pack2(Wn[t0 * OUTD + j], Wn[(t0 + 1) * OUTD + j]);
    }
    const float a1r = d_a1[tid];
    const float c1r = d_c1[tid];

    float s = 0.f, q = 0.f;
    for (int n = blockIdx.x; n < NN; n += gridDim.x) {
        __syncthreads();
        const float mz = d_maxZ[(size_t)n * TT + tid];
        const float mn = d_minZ[(size_t)n * TT + tid];
        pos[tid] = fmaf(a1r, (a1r >= 0.f ? mz : mn), c1r);
        __syncthreads();
        const ulonglong2* xr = (const ulonglong2*)(pos + half * FF);
        u64 acc0 = 0ull, acc1 = 0ull;
#pragma unroll
        for (int i = 0; i < FF / 4; ++i) {
            ulonglong2 xv = xr[i];
            fma2(acc0, xv.x, w2[2 * i]);
            fma2(acc1, xv.y, w2[2 * i + 1]);
        }
        float2 fa = unpack2(acc0), fb = unpack2(acc1);
        sred[tid] = (fa.x + fa.y) + (fb.x + fb.y);
        __syncthreads();
        if (tid < 128) {
            float v = sred[tid] + sred[tid + 128];
            d_PW[(size_t)n * OUTD + tid] = v;
            s += v;
            q = fmaf(v, v, q);
        }
    }
    if (tid < 128) {
        d_pC2s[blockIdx.x * 128 + tid] = s;
        d_pC2q[blockIdx.x * 128 + tid] = q;
    }
}

// ---------------- stats2: BN2 affine a2,c2 over concat columns ----------------
__global__ void stats2(const float* __restrict__ g2, const float* __restrict__ b2) {
    const int t = threadIdx.x;  // 256
    double s = 0.0, q = 0.0;
    if (t < 128) {
        for (int b = 0; b < NBLK; ++b) {
            s += (double)d_pC1s[b * 256 + t] + (double)d_pC1s[b * 256 + 128 + t];
            q += (double)d_pC1q[b * 256 + t] + (double)d_pC1q[b * 256 + 128 + t];
        }
    } else {
        const int jr = t - 128;
        for (int b = 0; b < NBLK; ++b) {
            s += (double)d_pC2s[b * 128 + jr];
            q += (double)d_pC2q[b * 128 + jr];
        }
    }
    const double inv = 1.0 / (double)NN;
    const double m = s * inv;
    const double var = q * inv - m * m;
    const float a = g2[t] * rsqrtf((float)var + EPSB);
    d_a2[t] = a;
    d_c2[t] = b2[t] - a * (float)m;
}

// ---------------- pass E: out = relu(a2 * concat(SW, PW) + c2) ----------------
__global__ void passE(float* __restrict__ out) {
    const int idx = blockIdx.x * blockDim.x + threadIdx.x;  // over NN*64 float4s
    if (idx >= NN * 64) return;
    const int n = idx >> 6;
    const int c4 = idx & 63;
    float4 v;
    if (c4 < 32) v = ((const float4*)d_SW)[(size_t)n * 32 + c4];
    else         v = ((const float4*)d_PW)[(size_t)n * 32 + (c4 - 32)];
    const float4 a = ((const float4*)d_a2)[c4];
    const float4 c = ((const float4*)d_c2)[c4];
    float4 r;
    r.x = fmaxf(0.f, fmaf(a.x, v.x, c.x));
    r.y = fmaxf(0.f, fmaf(a.y, v.y, c.y));
    r.z = fmaxf(0.f, fmaf(a.z, v.z, c.z));
    r.w = fmaxf(0.f, fmaf(a.w, v.w, c.w));
    ((float4*)out)[idx] = r;
}

// ---------------- launch ----------------
extern "C" void kernel_launch(void* const* d_in, const int* in_sizes, int n_in,
                              void* d_out, int out_size) {
    const float* selfn = (const float*)d_in[0];   // [N,128]
    const float* neigh = (const float*)d_in[1];   // [N,25,128]
    // d_in[2] len_adj_nodes: unused by reference
    const float* Wt = (const float*)d_in[3];      // [128,256]
    // d_in[4] bt: cancels exactly inside BN1
    const float* g1 = (const float*)d_in[5];
    const float* b1 = (const float*)d_in[6];
    const float* Wn = (const float*)d_in[7];      // [256,128]
    const float* Ws = (const float*)d_in[8];      // [128,128]
    const float* g2 = (const float*)d_in[9];
    const float* b2 = (const float*)d_in[10];
    float* out = (float*)d_out;

    passB<<<NBLK, 256>>>(neigh, Wt);
    stats1<<<1, 256>>>(g1, b1);
    passC1<<<NBLK, 256>>>(selfn, Ws);
    passC2<<<NBLK, 256>>>(Wn);
    stats2<<<1, 256>>>(g2, b2);
    passE<<<(NN * 64 + 255) / 256, 256>>>(out);
}

// round 3
// speedup vs baseline: 3.5786x; 3.5786x over previous
#include <cuda_runtime.h>
#include <cuda_bf16.h>
#include <cstdint>

#define NN   50000
#define KK   25
#define FF   128
#define TT   256
#define OUTD 128
#define NBLK 148
#define NKTOT 1250000
#define EPSB 1e-3f
#define NTILES (NN / 5)          /* 10000 */
#define ROWS_T 125               /* 5 nodes * 25 */

typedef unsigned long long u64;
typedef unsigned int u32;

// ---------------- smem layout for passB ----------------
// A tiles: 128 rows x 128 bf16, padded row stride 272B (17 x 16B -> conflict-free ldmatrix)
// B tiles: 128 k-rows x 256 bf16, padded row stride 528B (33 x 16B)
// zbuf (epilogue, fp32 128x130) aliases the A region (rebuilt every tile).
#define SM_AHI  0
#define SM_ALO  34816
#define SM_BHI  69632
#define SM_BLO  137216
#define SM_TOTAL 204800
#define ASTR 272
#define BSTR 528
#define ZSTRIDE 130

// ---------------- scratch ----------------
__device__ float d_maxZ[(size_t)NN * TT];
__device__ float d_minZ[(size_t)NN * TT];
__device__ float d_SW[(size_t)NN * OUTD];
__device__ float d_PW[(size_t)NN * OUTD];
__device__ float d_pBs2[NBLK * 2 * 256];
__device__ float d_pBq2[NBLK * 2 * 256];
__device__ float d_pC1s[NBLK * 256];
__device__ float d_pC1q[NBLK * 256];
__device__ float d_pC2s[NBLK * 128];
__device__ float d_pC2q[NBLK * 128];
__device__ float d_a1[TT], d_c1[TT];
__device__ float d_a2[256], d_c2[256];

// ---------------- helpers ----------------
__device__ __forceinline__ u32 smem_u32(const void* p) {
    u32 a;
    asm("{ .reg .u64 t; cvta.to.shared.u64 t, %1; cvt.u32.u64 %0, t; }" : "=r"(a) : "l"(p));
    return a;
}
__device__ __forceinline__ unsigned short f2bf(float x) {
    return __bfloat16_as_ushort(__float2bfloat16(x));
}
__device__ __forceinline__ float bf2f(unsigned short u) {
    return __bfloat162float(__ushort_as_bfloat16(u));
}
__device__ __forceinline__ void ldsm4(u32 a, u32& r0, u32& r1, u32& r2, u32& r3) {
    asm volatile("ldmatrix.sync.aligned.m8n8.x4.shared.b16 {%0,%1,%2,%3}, [%4];"
                 : "=r"(r0), "=r"(r1), "=r"(r2), "=r"(r3) : "r"(a));
}
__device__ __forceinline__ void ldsm4t(u32 a, u32& r0, u32& r1, u32& r2, u32& r3) {
    asm volatile("ldmatrix.sync.aligned.m8n8.x4.trans.shared.b16 {%0,%1,%2,%3}, [%4];"
                 : "=r"(r0), "=r"(r1), "=r"(r2), "=r"(r3) : "r"(a));
}
__device__ __forceinline__ void mma16816(float* d, const u32* a, u32 b0, u32 b1) {
    asm volatile(
        "mma.sync.aligned.m16n8k16.row.col.f32.bf16.bf16.f32 "
        "{%0,%1,%2,%3}, {%4,%5,%6,%7}, {%8,%9}, {%0,%1,%2,%3};"
        : "+f"(d[0]), "+f"(d[1]), "+f"(d[2]), "+f"(d[3])
        : "r"(a[0]), "r"(a[1]), "r"(a[2]), "r"(a[3]), "r"(b0), "r"(b1));
}

// ================= pass B: HMMA bf16-split GEMM + segmented max/min/sums =================
__global__ void __launch_bounds__(256, 1)
passB(const float* __restrict__ neigh, const float* __restrict__ Wt) {
    extern __shared__ char smem[];
    const u32 sb = smem_u32(smem);
    const int tid = threadIdx.x;
    const int wid = tid >> 5;
    const int lane = tid & 31;
    const int g8 = lane >> 2;          // group id (row within 8)
    const int tig = lane & 3;          // thread in group
    const int mwarp = wid & 3;         // m-block (32 rows)
    const int nwarp = wid >> 2;        // n-half (128 cols)
    const int m0 = mwarp * 32;
    const int n0 = nwarp * 128;
    float* zbuf = (float*)smem;

    // ---- B = Wt (hi/lo split) into SMEM once: Wt is [K=128][N=256] row-major ----
    for (int idx = tid; idx < FF * 64; idx += 256) {    // float4 over Wt
        int k = idx >> 6, n4 = idx & 63;
        float4 v = ((const float4*)Wt)[idx];
        unsigned short h0 = f2bf(v.x), h1 = f2bf(v.y), h2 = f2bf(v.z), h3 = f2bf(v.w);
        uint2 uh, ul;
        uh.x = (u32)h0 | ((u32)h1 << 16);
        uh.y = (u32)h2 | ((u32)h3 << 16);
        ul.x = (u32)f2bf(v.x - bf2f(h0)) | ((u32)f2bf(v.y - bf2f(h1)) << 16);
        ul.y = (u32)f2bf(v.z - bf2f(h2)) | ((u32)f2bf(v.w - bf2f(h3)) << 16);
        *(uint2*)(smem + SM_BHI + k * BSTR + n4 * 8) = uh;
        *(uint2*)(smem + SM_BLO + k * BSTR + n4 * 8) = ul;
    }

    // ldmatrix lane addressing (precompute per-lane row/col pieces)
    const int a_row_l = lane & 15;            // row within 16
    const int a_koff  = (lane >> 4) << 3;     // 0 or 8 (k chunk)
    float sAcc[2] = {0.f, 0.f}, qAcc[2] = {0.f, 0.f};

    for (int gt = blockIdx.x; gt < NTILES; gt += NBLK) {
        __syncthreads();   // zbuf readers (prev tile) done before A overwrite

        // ---- convert A tile: 125 rows x 128 f32 -> bf16 hi/lo ----
        const float4* src = (const float4*)(neigh + (size_t)gt * (ROWS_T * FF));
        for (int idx = tid; idx < ROWS_T * 32; idx += 256) {
            float4 v = src[idx];
            int r = idx >> 5, c4 = idx & 31;
            unsigned short h0 = f2bf(v.x), h1 = f2bf(v.y), h2 = f2bf(v.z), h3 = f2bf(v.w);
            uint2 uh, ul;
            uh.x = (u32)h0 | ((u32)h1 << 16);
            uh.y = (u32)h2 | ((u32)h3 << 16);
            ul.x = (u32)f2bf(v.x - bf2f(h0)) | ((u32)f2bf(v.y - bf2f(h1)) << 16);
            ul.y = (u32)f2bf(v.z - bf2f(h2)) | ((u32)f2bf(v.w - bf2f(h3)) << 16);
            *(uint2*)(smem + SM_AHI + r * ASTR + c4 * 8) = uh;
            *(uint2*)(smem + SM_ALO + r * ASTR + c4 * 8) = ul;
        }
        __syncthreads();

        // ---- MMA mainloop ----
        float acc[2][16][4];
#pragma unroll
        for (int mt = 0; mt < 2; ++mt)
#pragma unroll
            for (int nt = 0; nt < 16; ++nt)
#pragma unroll
                for (int i = 0; i < 4; ++i) acc[mt][nt][i] = 0.f;

#pragma unroll
        for (int s = 0; s < 8; ++s) {
            u32 ah[2][4], al[2][4];
#pragma unroll
            for (int mt = 0; mt < 2; ++mt) {
                u32 off = (u32)((m0 + mt * 16 + a_row_l) * ASTR + (s * 16 + a_koff) * 2);
                ldsm4(sb + SM_AHI + off, ah[mt][0], ah[mt][1], ah[mt][2], ah[mt][3]);
                ldsm4(sb + SM_ALO + off, al[mt][0], al[mt][1], al[mt][2], al[mt][3]);
            }
#pragma unroll
            for (int nt2 = 0; nt2 < 8; ++nt2) {
                u32 bh[4], bl[4];
                u32 boff = (u32)((s * 16 + a_row_l) * BSTR + (n0 + nt2 * 16 + a_koff) * 2);
                ldsm4t(sb + SM_BHI + boff, bh[0], bh[1], bh[2], bh[3]);
                ldsm4t(sb + SM_BLO + boff, bl[0], bl[1], bl[2], bl[3]);
#pragma unroll
                for (int mt = 0; mt < 2; ++mt) {
                    mma16816(acc[mt][nt2 * 2],     ah[mt], bh[0], bh[1]);
                    mma16816(acc[mt][nt2 * 2],     ah[mt], bl[0], bl[1]);
                    mma16816(acc[mt][nt2 * 2],     al[mt], bh[0], bh[1]);
                    mma16816(acc[mt][nt2 * 2 + 1], ah[mt], bh[2], bh[3]);
                    mma16816(acc[mt][nt2 * 2 + 1], ah[mt], bl[2], bl[3]);
                    mma16816(acc[mt][nt2 * 2 + 1], al[mt], bh[2], bh[3]);
                }
            }
        }
        __syncthreads();   // all ldmatrix reads of A done before zbuf (aliases A) writes

        // ---- epilogue: two n-halves through zbuf ----
#pragma unroll
        for (int h = 0; h < 2; ++h) {
            if (nwarp == h) {
#pragma unroll
                for (int mt = 0; mt < 2; ++mt)
#pragma unroll
                    for (int nt = 0; nt < 16; ++nt) {
                        int row = m0 + mt * 16 + g8;
                        int col = nt * 8 + tig * 2;
                        float2 lo2; lo2.x = acc[mt][nt][0]; lo2.y = acc[mt][nt][1];
                        float2 hi2; hi2.x = acc[mt][nt][2]; hi2.y = acc[mt][nt][3];
                        *(float2*)(zbuf + row * ZSTRIDE + col) = lo2;
                        *(float2*)(zbuf + (row + 8) * ZSTRIDE + col) = hi2;
                    }
            }
            __syncthreads();
            for (int task = tid; task < 640; task += 256) {
                const int grp = task >> 7;     // node within tile (0..4)
                const int col = task & 127;
                const float* zb = zbuf + grp * 25 * ZSTRIDE + col;
                float mx = -3.4e38f, mn = 3.4e38f, s = 0.f, q = 0.f;
#pragma unroll
                for (int r = 0; r < 25; ++r) {
                    float v = zb[r * ZSTRIDE];
                    mx = fmaxf(mx, v);
                    mn = fminf(mn, v);
                    s += v;
                    q = fmaf(v, v, q);
                }
                const size_t node = (size_t)(5 * gt + grp);
                d_maxZ[node * TT + h * 128 + col] = mx;
                d_minZ[node * TT + h * 128 + col] = mn;
                sAcc[h] += s;
                qAcc[h] += q;
            }
            __syncthreads();
        }
    }

    // per-thread partials -> deterministic slots [blk][b=tid>>7][h*128 + col]
    {
        const int b = tid >> 7, col = tid & 127;
#pragma unroll
        for (int h = 0; h < 2; ++h) {
            d_pBs2[blockIdx.x * 512 + b * 256 + h * 128 + col] = sAcc[h];
            d_pBq2[blockIdx.x * 512 + b * 256 + h * 128 + col] = qAcc[h];
        }
    }
}

// ---------------- packed fp32x2 helpers ----------------
__device__ __forceinline__ u64 pack2(float lo, float hi) {
    u64 r;
    asm("mov.b64 %0, {%1, %2};" : "=l"(r) : "f"(lo), "f"(hi));
    return r;
}
__device__ __forceinline__ void fma2(u64& acc, u64 a, u64 b) {
    asm("fma.rn.f32x2 %0, %1, %2, %0;" : "+l"(acc) : "l"(a), "l"(b));
}
__device__ __forceinline__ float2 unpack2(u64 v) {
    float lo, hi;
    asm("mov.b64 {%0, %1}, %2;" : "=f"(lo), "=f"(hi) : "l"(v));
    return make_float2(lo, hi);
}

// ---------------- stats1 ----------------
__global__ void stats1(const float* __restrict__ g1, const float* __restrict__ b1) {
    const int t = threadIdx.x;  // 256
    double s = 0.0, q = 0.0;
    for (int i = 0; i < NBLK * 2; ++i) {
        s += (double)d_pBs2[i * 256 + t];
        q += (double)d_pBq2[i * 256 + t];
    }
    const double inv = 1.0 / (double)NKTOT;
    const double m = s * inv;
    const double var = q * inv - m * m;
    const float a = g1[t] * rsqrtf((float)var + EPSB);
    d_a1[t] = a;
    d_c1[t] = b1[t] - a * (float)m;
}

// ---------------- pass C1: SW = self @ Ws ; column sums ----------------
__global__ void __launch_bounds__(256, 1)
passC1(const float* __restrict__ selfn, const float* __restrict__ Ws) {
    __shared__ float4 xs4[2 * FF / 4];
    float* xs = (float*)xs4;
    const int tid = threadIdx.x;
    const int which = tid >> 7;
    const int j = tid & 127;

    u64 w2[FF / 2];
#pragma unroll
    for (int i = 0; i < FF / 2; ++i)
        w2[i] = pack2(Ws[(2 * i) * OUTD + j], Ws[(2 * i + 1) * OUTD + j]);

    float s = 0.f, q = 0.f;
    for (int base = blockIdx.x * 2; base < NN; base += gridDim.x * 2) {
        __syncthreads();
        xs[tid] = selfn[(size_t)base * FF + tid];
        __syncthreads();
        const ulonglong2* xr = (const ulonglong2*)(xs + which * FF);
        u64 acc0 = 0ull, acc1 = 0ull;
#pragma unroll
        for (int i = 0; i < FF / 4; ++i) {
            ulonglong2 xv = xr[i];
            fma2(acc0, xv.x, w2[2 * i]);
            fma2(acc1, xv.y, w2[2 * i + 1]);
        }
        float2 fa = unpack2(acc0), fb = unpack2(acc1);
        float z = (fa.x + fa.y) + (fb.x + fb.y);
        d_SW[(size_t)(base + which) * OUTD + j] = z;
        s += z;
        q = fmaf(z, z, q);
    }
    d_pC1s[blockIdx.x * 256 + tid] = s;
    d_pC1q[blockIdx.x * 256 + tid] = q;
}

// ---------------- pass C2: pooled = a1*max|min + c1 ; PW = pooled @ Wn ----------------
__global__ void __launch_bounds__(256, 1)
passC2(const float* __restrict__ Wn) {
    __shared__ float4 pos4[TT / 4];
    __shared__ float4 sred4[256 / 4];
    float* pos = (float*)pos4;
    float* sred = (float*)sred4;
    const int tid = threadIdx.x;
    const int half = tid >> 7;
    const int j = tid & 127;

    u64 w2[FF / 2];
#pragma unroll
    for (int i = 0; i < FF / 2; ++i) {
        int t0 = half * 128 + 2 * i;
        w2[i] = pack2(Wn[t0 * OUTD + j], Wn[(t0 + 1) * OUTD + j]);
    }
    const float a1r = d_a1[tid];
    const float c1r = d_c1[tid];

    float s = 0.f, q = 0.f;
    for (int n = blockIdx.x; n < NN; n += gridDim.x) {
        __syncthreads();
        const float mz = d_maxZ[(size_t)n * TT + tid];
        const float mn = d_minZ[(size_t)n * TT + tid];
        pos[tid] = fmaf(a1r, (a1r >= 0.f ? mz : mn), c1r);
        __syncthreads();
        const ulonglong2* xr = (const ulonglong2*)(pos + half * FF);
        u64 acc0 = 0ull, acc1 = 0ull;
#pragma unroll
        for (int i = 0; i < FF / 4; ++i) {
            ulonglong2 xv = xr[i];
            fma2(acc0, xv.x, w2[2 * i]);
            fma2(acc1, xv.y, w2[2 * i + 1]);
        }
        float2 fa = unpack2(acc0), fb = unpack2(acc1);
        sred[tid] = (fa.x + fa.y) + (fb.x + fb.y);
        __syncthreads();
        if (tid < 128) {
            float v = sred[tid] + sred[tid + 128];
            d_PW[(size_t)n * OUTD + tid] = v;
            s += v;
            q = fmaf(v, v, q);
        }
    }
    if (tid < 128) {
        d_pC2s[blockIdx.x * 128 + tid] = s;
        d_pC2q[blockIdx.x * 128 + tid] = q;
    }
}

// ---------------- stats2 ----------------
__global__ void stats2(const float* __restrict__ g2, const float* __restrict__ b2) {
    const int t = threadIdx.x;  // 256
    double s = 0.0, q = 0.0;
    if (t < 128) {
        for (int b = 0; b < NBLK; ++b) {
            s += (double)d_pC1s[b * 256 + t] + (double)d_pC1s[b * 256 + 128 + t];
            q += (double)d_pC1q[b * 256 + t] + (double)d_pC1q[b * 256 + 128 + t];
        }
    } else {
        const int jr = t - 128;
        for (int b = 0; b < NBLK; ++b) {
            s += (double)d_pC2s[b * 128 + jr];
            q += (double)d_pC2q[b * 128 + jr];
        }
    }
    const double inv = 1.0 / (double)NN;
    const double m = s * inv;
    const double var = q * inv - m * m;
    const float a = g2[t] * rsqrtf((float)var + EPSB);
    d_a2[t] = a;
    d_c2[t] = b2[t] - a * (float)m;
}

// ---------------- pass E ----------------
__global__ void passE(float* __restrict__ out) {
    const int idx = blockIdx.x * blockDim.x + threadIdx.x;
    if (idx >= NN * 64) return;
    const int n = idx >> 6;
    const int c4 = idx & 63;
    float4 v;
    if (c4 < 32) v = ((const float4*)d_SW)[(size_t)n * 32 + c4];
    else         v = ((const float4*)d_PW)[(size_t)n * 32 + (c4 - 32)];
    const float4 a = ((const float4*)d_a2)[c4];
    const float4 c = ((const float4*)d_c2)[c4];
    float4 r;
    r.x = fmaxf(0.f, fmaf(a.x, v.x, c.x));
    r.y = fmaxf(0.f, fmaf(a.y, v.y, c.y));
    r.z = fmaxf(0.f, fmaf(a.z, v.z, c.z));
    r.w = fmaxf(0.f, fmaf(a.w, v.w, c.w));
    ((float4*)out)[idx] = r;
}

// ---------------- launch ----------------
extern "C" void kernel_launch(void* const* d_in, const int* in_sizes, int n_in,
                              void* d_out, int out_size) {
    const float* selfn = (const float*)d_in[0];
    const float* neigh = (const float*)d_in[1];
    const float* Wt = (const float*)d_in[3];
    const float* g1 = (const float*)d_in[5];
    const float* b1 = (const float*)d_in[6];
    const float* Wn = (const float*)d_in[7];
    const float* Ws = (const float*)d_in[8];
    const float* g2 = (const float*)d_in[9];
    const float* b2 = (const float*)d_in[10];
    float* out = (float*)d_out;

    static int configured = 0;
    if (!configured) {
        cudaFuncSetAttribute(passB, cudaFuncAttributeMaxDynamicSharedMemorySize, SM_TOTAL);
        configured = 1;
    }

    passB<<<NBLK, 256, SM_TOTAL>>>(neigh, Wt);
    stats1<<<1, 256>>>(g1, b1);
    passC1<<<NBLK, 256>>>(selfn, Ws);
    passC2<<<NBLK, 256>>>(Wn);
    stats2<<<1, 256>>>(g2, b2);
    passE<<<(NN * 64 + 255) / 256, 256>>>(out);
}

// round 5
// speedup vs baseline: 4.1398x; 1.1568x over previous
#include <cuda_runtime.h>
#include <cuda_bf16.h>
#include <cstdint>

#define NN   50000
#define KK   25
#define FF   128
#define TT   256
#define OUTD 128
#define NBLK 148
#define NKTOT 1250000
#define EPSB 1e-3f
#define NTILES (NN / 5)          /* 10000 */
#define ROWS_T 125               /* 5 nodes * 25 */

typedef unsigned long long u64;
typedef unsigned int u32;

// ---------------- smem layout for passB ----------------
#define SM_AHI  0
#define SM_ALO  34816
#define SM_BHI  69632
#define SM_BLO  137216
#define SM_TOTAL 204800
#define ASTR 272
#define BSTR 528
#define ZSTRIDE 130

// ---------------- scratch ----------------
__device__ float d_poolZ[(size_t)NN * TT];
__device__ float d_SW[(size_t)NN * OUTD];
__device__ float d_PW[(size_t)NN * OUTD];
__device__ float d_pBs2[NBLK * 2 * 256];
__device__ float d_pBq2[NBLK * 2 * 256];
__device__ float d_pC1s[NBLK * 256];
__device__ float d_pC1q[NBLK * 256];
__device__ float d_pC2s[NBLK * 256];
__device__ float d_pC2q[NBLK * 256];
__device__ float d_a1[TT], d_c1[TT];
__device__ float d_a2[256], d_c2[256];

// ---------------- helpers ----------------
__device__ __forceinline__ u32 smem_u32(const void* p) {
    u32 a;
    asm("{ .reg .u64 t; cvta.to.shared.u64 t, %1; cvt.u32.u64 %0, t; }" : "=r"(a) : "l"(p));
    return a;
}
__device__ __forceinline__ unsigned short f2bf(float x) {
    return __bfloat16_as_ushort(__float2bfloat16(x));
}
__device__ __forceinline__ float bf2f(unsigned short u) {
    return __bfloat162float(__ushort_as_bfloat16(u));
}
__device__ __forceinline__ void ldsm4(u32 a, u32& r0, u32& r1, u32& r2, u32& r3) {
    asm volatile("ldmatrix.sync.aligned.m8n8.x4.shared.b16 {%0,%1,%2,%3}, [%4];"
                 : "=r"(r0), "=r"(r1), "=r"(r2), "=r"(r3) : "r"(a));
}
__device__ __forceinline__ void ldsm4t(u32 a, u32& r0, u32& r1, u32& r2, u32& r3) {
    asm volatile("ldmatrix.sync.aligned.m8n8.x4.trans.shared.b16 {%0,%1,%2,%3}, [%4];"
                 : "=r"(r0), "=r"(r1), "=r"(r2), "=r"(r3) : "r"(a));
}
__device__ __forceinline__ void mma16816(float* d, const u32* a, u32 b0, u32 b1) {
    asm volatile(
        "mma.sync.aligned.m16n8k16.row.col.f32.bf16.bf16.f32 "
        "{%0,%1,%2,%3}, {%4,%5,%6,%7}, {%8,%9}, {%0,%1,%2,%3};"
        : "+f"(d[0]), "+f"(d[1]), "+f"(d[2]), "+f"(d[3])
        : "r"(a[0]), "r"(a[1]), "r"(a[2]), "r"(a[3]), "r"(b0), "r"(b1));
}
__device__ __forceinline__ u64 pack2(float lo, float hi) {
    u64 r;
    asm("mov.b64 %0, {%1, %2};" : "=l"(r) : "f"(lo), "f"(hi));
    return r;
}
__device__ __forceinline__ void fma2(u64& acc, u64 a, u64 b) {
    asm("fma.rn.f32x2 %0, %1, %2, %0;" : "+l"(acc) : "l"(a), "l"(b));
}
__device__ __forceinline__ float2 unpack2(u64 v) {
    float lo, hi;
    asm("mov.b64 {%0, %1}, %2;" : "=f"(lo), "=f"(hi) : "l"(v));
    return make_float2(lo, hi);
}

// ================= pass B: HMMA bf16-split GEMM + pooled select by sign(g1) =================
__global__ void __launch_bounds__(256, 1)
passB(const float* __restrict__ neigh, const float* __restrict__ Wt,
      const float* __restrict__ g1) {
    extern __shared__ char smem[];
    const u32 sb = smem_u32(smem);
    const int tid = threadIdx.x;
    const int wid = tid >> 5;
    const int lane = tid & 31;
    const int g8 = lane >> 2;
    const int tig = lane & 3;
    const int mwarp = wid & 3;
    const int nwarp = wid >> 2;
    const int m0 = mwarp * 32;
    const int n0 = nwarp * 128;
    float* zbuf = (float*)smem;

    // ---- B = Wt (hi/lo split) into SMEM once ----
    for (int idx = tid; idx < FF * 64; idx += 256) {
        int k = idx >> 6, n4 = idx & 63;
        float4 v = ((const float4*)Wt)[idx];
        unsigned short h0 = f2bf(v.x), h1 = f2bf(v.y), h2 = f2bf(v.z), h3 = f2bf(v.w);
        uint2 uh, ul;
        uh.x = (u32)h0 | ((u32)h1 << 16);
        uh.y = (u32)h2 | ((u32)h3 << 16);
        ul.x = (u32)f2bf(v.x - bf2f(h0)) | ((u32)f2bf(v.y - bf2f(h1)) << 16);
        ul.y = (u32)f2bf(v.z - bf2f(h2)) | ((u32)f2bf(v.w - bf2f(h3)) << 16);
        *(uint2*)(smem + SM_BHI + k * BSTR + n4 * 8) = uh;
        *(uint2*)(smem + SM_BLO + k * BSTR + n4 * 8) = ul;
    }

    const int a_row_l = lane & 15;
    const int a_koff  = (lane >> 4) << 3;
    float sAcc[2] = {0.f, 0.f}, qAcc[2] = {0.f, 0.f};

    for (int gt = blockIdx.x; gt < NTILES; gt += NBLK) {
        __syncthreads();

        // ---- convert A tile ----
        const float4* src = (const float4*)(neigh + (size_t)gt * (ROWS_T * FF));
        for (int idx = tid; idx < ROWS_T * 32; idx += 256) {
            float4 v = src[idx];
            int r = idx >> 5, c4 = idx & 31;
            unsigned short h0 = f2bf(v.x), h1 = f2bf(v.y), h2 = f2bf(v.z), h3 = f2bf(v.w);
            uint2 uh, ul;
            uh.x = (u32)h0 | ((u32)h1 << 16);
            uh.y = (u32)h2 | ((u32)h3 << 16);
            ul.x = (u32)f2bf(v.x - bf2f(h0)) | ((u32)f2bf(v.y - bf2f(h1)) << 16);
            ul.y = (u32)f2bf(v.z - bf2f(h2)) | ((u32)f2bf(v.w - bf2f(h3)) << 16);
            *(uint2*)(smem + SM_AHI + r * ASTR + c4 * 8) = uh;
            *(uint2*)(smem + SM_ALO + r * ASTR + c4 * 8) = ul;
        }
        __syncthreads();

        // ---- MMA mainloop ----
        float acc[2][16][4];
#pragma unroll
        for (int mt = 0; mt < 2; ++mt)
#pragma unroll
            for (int nt = 0; nt < 16; ++nt)
#pragma unroll
                for (int i = 0; i < 4; ++i) acc[mt][nt][i] = 0.f;

#pragma unroll
        for (int s = 0; s < 8; ++s) {
            u32 ah[2][4], al[2][4];
#pragma unroll
            for (int mt = 0; mt < 2; ++mt) {
                u32 off = (u32)((m0 + mt * 16 + a_row_l) * ASTR + (s * 16 + a_koff) * 2);
                ldsm4(sb + SM_AHI + off, ah[mt][0], ah[mt][1], ah[mt][2], ah[mt][3]);
                ldsm4(sb + SM_ALO + off, al[mt][0], al[mt][1], al[mt][2], al[mt][3]);
            }
#pragma unroll
            for (int nt2 = 0; nt2 < 8; ++nt2) {
                u32 bh[4], bl[4];
                u32 boff = (u32)((s * 16 + a_row_l) * BSTR + (n0 + nt2 * 16 + a_koff) * 2);
                ldsm4t(sb + SM_BHI + boff, bh[0], bh[1], bh[2], bh[3]);
                ldsm4t(sb + SM_BLO + boff, bl[0], bl[1], bl[2], bl[3]);
#pragma unroll
                for (int mt = 0; mt < 2; ++mt) {
                    mma16816(acc[mt][nt2 * 2],     ah[mt], bh[0], bh[1]);
                    mma16816(acc[mt][nt2 * 2],     ah[mt], bl[0], bl[1]);
                    mma16816(acc[mt][nt2 * 2],     al[mt], bh[0], bh[1]);
                    mma16816(acc[mt][nt2 * 2 + 1], ah[mt], bh[2], bh[3]);
                    mma16816(acc[mt][nt2 * 2 + 1], ah[mt], bl[2], bl[3]);
                    mma16816(acc[mt][nt2 * 2 + 1], al[mt], bh[2], bh[3]);
                }
            }
        }
        __syncthreads();

        // ---- epilogue: pooled select by sign(g1) + sums ----
#pragma unroll
        for (int h = 0; h < 2; ++h) {
            if (nwarp == h) {
#pragma unroll
                for (int mt = 0; mt < 2; ++mt)
#pragma unroll
                    for (int nt = 0; nt < 16; ++nt) {
                        int row = m0 + mt * 16 + g8;
                        int col = nt * 8 + tig * 2;
                        float2 lo2; lo2.x = acc[mt][nt][0]; lo2.y = acc[mt][nt][1];
                        float2 hi2; hi2.x = acc[mt][nt][2]; hi2.y = acc[mt][nt][3];
                        *(float2*)(zbuf + row * ZSTRIDE + col) = lo2;
                        *(float2*)(zbuf + (row + 8) * ZSTRIDE + col) = hi2;
                    }
            }
            __syncthreads();
            for (int task = tid; task < 640; task += 256) {
                const int grp = task >> 7;
                const int col = task & 127;
                const float* zb = zbuf + grp * 25 * ZSTRIDE + col;
                float mx = -3.4e38f, mn = 3.4e38f, s = 0.f, q = 0.f;
#pragma unroll
                for (int r = 0; r < 25; ++r) {
                    float v = zb[r * ZSTRIDE];
                    mx = fmaxf(mx, v);
                    mn = fminf(mn, v);
                    s += v;
                    q = fmaf(v, v, q);
                }
                const size_t node = (size_t)(5 * gt + grp);
                const float g1v = __ldg(&g1[h * 128 + col]);
                d_poolZ[node * TT + h * 128 + col] = (g1v >= 0.f) ? mx : mn;
                sAcc[h] += s;
                qAcc[h] += q;
            }
            __syncthreads();
        }
    }

    {
        const int b = tid >> 7, col = tid & 127;
#pragma unroll
        for (int h = 0; h < 2; ++h) {
            d_pBs2[blockIdx.x * 512 + b * 256 + h * 128 + col] = sAcc[h];
            d_pBq2[blockIdx.x * 512 + b * 256 + h * 128 + col] = qAcc[h];
        }
    }
}

// ---------------- stats1: 512 threads, split rows ----------------
__global__ void stats1(const float* __restrict__ g1, const float* __restrict__ b1) {
    __shared__ double ss[512], qq[512];
    const int t = threadIdx.x & 255;
    const int half = threadIdx.x >> 8;
    double s = 0.0, q = 0.0;
    for (int i = half * NBLK; i < (half + 1) * NBLK; ++i) {
        s += (double)d_pBs2[i * 256 + t];
        q += (double)d_pBq2[i * 256 + t];
    }
    ss[threadIdx.x] = s; qq[threadIdx.x] = q;
    __syncthreads();
    if (half == 0) {
        s += ss[256 + t]; q += qq[256 + t];
        const double inv = 1.0 / (double)NKTOT;
        const double m = s * inv;
        const double var = q * inv - m * m;
        const float a = g1[t] * rsqrtf((float)var + EPSB);
        d_a1[t] = a;
        d_c1[t] = b1[t] - a * (float)m;
    }
}

// ---------------- merged pass C1+C2 (grid 2*NBLK) ----------------
__global__ void __launch_bounds__(256, 1)
passC12(const float* __restrict__ selfn, const float* __restrict__ Ws,
        const float* __restrict__ Wn) {
    __shared__ float sm[4096];
    const int tid = threadIdx.x;
    const int grp = tid >> 7;
    const int j = tid & 127;

    if (blockIdx.x < NBLK) {
        // ===== C1: SW = self @ Ws, 8 nodes per barrier pair =====
        const int bid = blockIdx.x;
        u64 w2[64];
#pragma unroll
        for (int i = 0; i < 64; ++i)
            w2[i] = pack2(Ws[(2 * i) * OUTD + j], Ws[(2 * i + 1) * OUTD + j]);

        float s = 0.f, q = 0.f;
        for (int base = bid * 8; base < NN; base += NBLK * 8) {
            __syncthreads();
#pragma unroll
            for (int k = 0; k < 4; ++k)
                sm[tid + k * 256] = selfn[(size_t)base * FF + tid + k * 256];
            __syncthreads();
#pragma unroll
            for (int nd = 0; nd < 4; ++nd) {
                const ulonglong2* xr = (const ulonglong2*)(sm + (grp * 4 + nd) * FF);
                u64 a0 = 0ull, a1 = 0ull;
#pragma unroll
                for (int i = 0; i < 32; ++i) {
                    ulonglong2 xv = xr[i];
                    fma2(a0, xv.x, w2[2 * i]);
                    fma2(a1, xv.y, w2[2 * i + 1]);
                }
                float2 fa = unpack2(a0), fb = unpack2(a1);
                float z = (fa.x + fa.y) + (fb.x + fb.y);
                d_SW[(size_t)(base + grp * 4 + nd) * OUTD + j] = z;
                s += z;
                q = fmaf(z, z, q);
            }
        }
        d_pC1s[bid * 256 + tid] = s;
        d_pC1q[bid * 256 + tid] = q;
    } else {
        // ===== C2: PW = (a1*poolZ + c1) @ Wn, affine folded into weights =====
        const int bid = blockIdx.x - NBLK;
        float* pos = sm;          // 2048 floats
        float* sred = sm + 2048;  // 2048 floats
        u64 w2[64];
        float cst = 0.f;
#pragma unroll
        for (int i = 0; i < 64; ++i) {
            const int t0 = grp * 128 + 2 * i;
            const float wa = Wn[t0 * OUTD + j];
            const float wb = Wn[(t0 + 1) * OUTD + j];
            w2[i] = pack2(d_a1[t0] * wa, d_a1[t0 + 1] * wb);
            cst += d_c1[t0] * wa + d_c1[t0 + 1] * wb;
        }

        float s = 0.f, q = 0.f;
        for (int base = bid * 8; base < NN; base += NBLK * 8) {
            __syncthreads();
#pragma unroll
            for (int k = 0; k < 8; ++k)
                pos[k * 256 + tid] = d_poolZ[(size_t)(base + k) * TT + tid];
            __syncthreads();
#pragma unroll
            for (int nd = 0; nd < 8; ++nd) {
                const ulonglong2* xr = (const ulonglong2*)(pos + nd * TT + grp * 128);
                u64 a0 = 0ull, a1v = 0ull;
#pragma unroll
                for (int i = 0; i < 32; ++i) {
                    ulonglong2 xv = xr[i];
                    fma2(a0, xv.x, w2[2 * i]);
                    fma2(a1v, xv.y, w2[2 * i + 1]);
                }
                float2 fa = unpack2(a0), fb = unpack2(a1v);
                sred[grp * 1024 + nd * 128 + j] = (fa.x + fa.y) + (fb.x + fb.y) + cst;
            }
            __syncthreads();
#pragma unroll
            for (int k = 0; k < 4; ++k) {
                const int o = tid + k * 256;
                const int nd = o >> 7;
                const float v = sred[nd * 128 + j] + sred[1024 + nd * 128 + j];
                d_PW[(size_t)(base + nd) * OUTD + j] = v;
                s += v;
                q = fmaf(v, v, q);
            }
        }
        d_pC2s[bid * 256 + tid] = s;
        d_pC2q[bid * 256 + tid] = q;
    }
}

// ---------------- stats2: 512 threads, split rows ----------------
__global__ void stats2(const float* __restrict__ g2, const float* __restrict__ b2) {
    __shared__ double ss[512], qq[512];
    const int c = threadIdx.x & 255;
    const int half = threadIdx.x >> 8;
    const int r0 = half * (NBLK / 2);
    const int r1 = r0 + (NBLK / 2);
    double s = 0.0, q = 0.0;
    if (c < 128) {
        for (int b = r0; b < r1; ++b) {
            s += (double)d_pC1s[b * 256 + c] + (double)d_pC1s[b * 256 + 128 + c];
            q += (double)d_pC1q[b * 256 + c] + (double)d_pC1q[b * 256 + 128 + c];
        }
    } else {
        const int jr = c - 128;
        for (int b = r0; b < r1; ++b) {
            s += (double)d_pC2s[b * 256 + jr] + (double)d_pC2s[b * 256 + 128 + jr];
            q += (double)d_pC2q[b * 256 + jr] + (double)d_pC2q[b * 256 + 128 + jr];
        }
    }
    ss[threadIdx.x] = s; qq[threadIdx.x] = q;
    __syncthreads();
    if (half == 0) {
        s += ss[256 + c]; q += qq[256 + c];
        const double inv = 1.0 / (double)NN;
        const double m = s * inv;
        const double var = q * inv - m * m;
        const float a = g2[c] * rsqrtf((float)var + EPSB);
        d_a2[c] = a;
        d_c2[c] = b2[c] - a * (float)m;
    }
}

// ---------------- pass E ----------------
__global__ void passE(float* __restrict__ out) {
    const int idx = blockIdx.x * blockDim.x + threadIdx.x;
    if (idx >= NN * 64) return;
    const int n = idx >> 6;
    const int c4 = idx & 63;
    float4 v;
    if (c4 < 32) v = ((const float4*)d_SW)[(size_t)n * 32 + c4];
    else         v = ((const float4*)d_PW)[(size_t)n * 32 + (c4 - 32)];
    const float4 a = ((const float4*)d_a2)[c4];
    const float4 c = ((const float4*)d_c2)[c4];
    float4 r;
    r.x = fmaxf(0.f, fmaf(a.x, v.x, c.x));
    r.y = fmaxf(0.f, fmaf(a.y, v.y, c.y));
    r.z = fmaxf(0.f, fmaf(a.z, v.z, c.z));
    r.w = fmaxf(0.f, fmaf(a.w, v.w, c.w));
    ((float4*)out)[idx] = r;
}

// ---------------- launch ----------------
extern "C" void kernel_launch(void* const* d_in, const int* in_sizes, int n_in,
                              void* d_out, int out_size) {
    const float* selfn = (const float*)d_in[0];
    const float* neigh = (const float*)d_in[1];
    const float* Wt = (const float*)d_in[3];
    const float* g1 = (const float*)d_in[5];
    const float* b1 = (const float*)d_in[6];
    const float* Wn = (const float*)d_in[7];
    const float* Ws = (const float*)d_in[8];
    const float* g2 = (const float*)d_in[9];
    const float* b2 = (const float*)d_in[10];
    float* out = (float*)d_out;

    static int configured = 0;
    if (!configured) {
        cudaFuncSetAttribute(passB, cudaFuncAttributeMaxDynamicSharedMemorySize, SM_TOTAL);
        configured = 1;
    }

    passB<<<NBLK, 256, SM_TOTAL>>>(neigh, Wt, g1);
    stats1<<<1, 512>>>(g1, b1);
    passC12<<<2 * NBLK, 256>>>(selfn, Ws, Wn);
    stats2<<<1, 512>>>(g2, b2);
    passE<<<(NN * 64 + 255) / 256, 256>>>(out);
}

// round 6
// speedup vs baseline: 4.8970x; 1.1829x over previous
#include <cuda_runtime.h>
#include <cuda_bf16.h>
#include <cstdint>

#define NN   50000
#define KK   25
#define FF   128
#define TT   256
#define OUTD 128
#define NBLK 148
#define NKTOT 1250000
#define EPSB 1e-3f
#define NTILES (NN / 5)          /* 10000 */
#define ROWS_T 125               /* 5 nodes * 25 */

typedef unsigned long long u64;
typedef unsigned int u32;

// ---------------- smem layout for passB ----------------
#define SM_AHI  0
#define SM_ALO  34816
#define SM_BHI  69632
#define SM_BLO  137216
#define SM_TOTAL 204800
#define ASTR 272
#define BSTR 528
#define ZSTRIDE 130

// ---------------- scratch ----------------
__device__ float d_poolZ[(size_t)NN * TT];
__device__ float d_SW[(size_t)NN * OUTD];
__device__ float d_PW[(size_t)NN * OUTD];
__device__ float d_pBs2[NBLK * 2 * 256];
__device__ float d_pBq2[NBLK * 2 * 256];
__device__ float d_pC1s[NBLK * 256];
__device__ float d_pC1q[NBLK * 256];
__device__ float d_pC2s[NBLK * 256];
__device__ float d_pC2q[NBLK * 256];
__device__ float d_a1[TT], d_c1[TT];
__device__ float d_a2[256], d_c2[256];

// ---------------- helpers ----------------
__device__ __forceinline__ u32 smem_u32(const void* p) {
    u32 a;
    asm("{ .reg .u64 t; cvta.to.shared.u64 t, %1; cvt.u32.u64 %0, t; }" : "=r"(a) : "l"(p));
    return a;
}
// pair convert: hi = {bf16(y),bf16(x)} packed; lo = residual pair
__device__ __forceinline__ void cvt_pair(float x, float y, u32& hi, u32& lo) {
    asm("cvt.rn.bf16x2.f32 %0, %1, %2;" : "=r"(hi) : "f"(y), "f"(x));
    float h0 = __uint_as_float(hi << 16);
    float h1 = __uint_as_float(hi & 0xFFFF0000u);
    asm("cvt.rn.bf16x2.f32 %0, %1, %2;" : "=r"(lo) : "f"(y - h1), "f"(x - h0));
}
__device__ __forceinline__ void ldsm4(u32 a, u32& r0, u32& r1, u32& r2, u32& r3) {
    asm volatile("ldmatrix.sync.aligned.m8n8.x4.shared.b16 {%0,%1,%2,%3}, [%4];"
                 : "=r"(r0), "=r"(r1), "=r"(r2), "=r"(r3) : "r"(a));
}
__device__ __forceinline__ void ldsm4t(u32 a, u32& r0, u32& r1, u32& r2, u32& r3) {
    asm volatile("ldmatrix.sync.aligned.m8n8.x4.trans.shared.b16 {%0,%1,%2,%3}, [%4];"
                 : "=r"(r0), "=r"(r1), "=r"(r2), "=r"(r3) : "r"(a));
}
__device__ __forceinline__ void mma16816(float* d, const u32* a, u32 b0, u32 b1) {
    asm volatile(
        "mma.sync.aligned.m16n8k16.row.col.f32.bf16.bf16.f32 "
        "{%0,%1,%2,%3}, {%4,%5,%6,%7}, {%8,%9}, {%0,%1,%2,%3};"
        : "+f"(d[0]), "+f"(d[1]), "+f"(d[2]), "+f"(d[3])
        : "r"(a[0]), "r"(a[1]), "r"(a[2]), "r"(a[3]), "r"(b0), "r"(b1));
}
__device__ __forceinline__ u64 pack2(float lo, float hi) {
    u64 r;
    asm("mov.b64 %0, {%1, %2};" : "=l"(r) : "f"(lo), "f"(hi));
    return r;
}
__device__ __forceinline__ void fma2(u64& acc, u64 a, u64 b) {
    asm("fma.rn.f32x2 %0, %1, %2, %0;" : "+l"(acc) : "l"(a), "l"(b));
}
__device__ __forceinline__ float2 unpack2(u64 v) {
    float lo, hi;
    asm("mov.b64 {%0, %1}, %2;" : "=f"(lo), "=f"(hi) : "l"(v));
    return make_float2(lo, hi);
}

// ================= pass B: HMMA bf16-split GEMM + pooled select by sign(g1) =================
__global__ void __launch_bounds__(256, 1)
passB(const float* __restrict__ neigh, const float* __restrict__ Wt,
      const float* __restrict__ g1) {
    extern __shared__ char smem[];
    const u32 sb = smem_u32(smem);
    const int tid = threadIdx.x;
    const int wid = tid >> 5;
    const int lane = tid & 31;
    const int g8 = lane >> 2;
    const int tig = lane & 3;
    const int mwarp = wid & 3;
    const int nwarp = wid >> 2;
    const int m0 = mwarp * 32;
    const int n0 = nwarp * 128;
    float* zbuf = (float*)smem;

    // ---- B = Wt (hi/lo split) into SMEM once ----
    for (int idx = tid; idx < FF * 64; idx += 256) {
        int k = idx >> 6, n4 = idx & 63;
        float4 v = ((const float4*)Wt)[idx];
        uint2 uh, ul;
        cvt_pair(v.x, v.y, uh.x, ul.x);
        cvt_pair(v.z, v.w, uh.y, ul.y);
        *(uint2*)(smem + SM_BHI + k * BSTR + n4 * 8) = uh;
        *(uint2*)(smem + SM_BLO + k * BSTR + n4 * 8) = ul;
    }

    const int a_row_l = lane & 15;
    const int a_koff  = (lane >> 4) << 3;
    float sAcc[2] = {0.f, 0.f}, qAcc[2] = {0.f, 0.f};

    for (int gt = blockIdx.x; gt < NTILES; gt += NBLK) {
        __syncthreads();

        // ---- convert A tile: 125 rows x 128 f32 -> bf16 hi/lo ----
        const float4* src = (const float4*)(neigh + (size_t)gt * (ROWS_T * FF));
        for (int idx = tid; idx < ROWS_T * 32; idx += 256) {
            float4 v = src[idx];
            int r = idx >> 5, c4 = idx & 31;
            uint2 uh, ul;
            cvt_pair(v.x, v.y, uh.x, ul.x);
            cvt_pair(v.z, v.w, uh.y, ul.y);
            *(uint2*)(smem + SM_AHI + r * ASTR + c4 * 8) = uh;
            *(uint2*)(smem + SM_ALO + r * ASTR + c4 * 8) = ul;
        }
        __syncthreads();

        // ---- MMA mainloop ----
        float acc[2][16][4];
#pragma unroll
        for (int mt = 0; mt < 2; ++mt)
#pragma unroll
            for (int nt = 0; nt < 16; ++nt)
#pragma unroll
                for (int i = 0; i < 4; ++i) acc[mt][nt][i] = 0.f;

#pragma unroll
        for (int s = 0; s < 8; ++s) {
            u32 ah[2][4], al[2][4];
#pragma unroll
            for (int mt = 0; mt < 2; ++mt) {
                u32 off = (u32)((m0 + mt * 16 + a_row_l) * ASTR + (s * 16 + a_koff) * 2);
                ldsm4(sb + SM_AHI + off, ah[mt][0], ah[mt][1], ah[mt][2], ah[mt][3]);
                ldsm4(sb + SM_ALO + off, al[mt][0], al[mt][1], al[mt][2], al[mt][3]);
            }
#pragma unroll
            for (int nt2 = 0; nt2 < 8; ++nt2) {
                u32 bh[4], bl[4];
                u32 boff = (u32)((s * 16 + a_row_l) * BSTR + (n0 + nt2 * 16 + a_koff) * 2);
                ldsm4t(sb + SM_BHI + boff, bh[0], bh[1], bh[2], bh[3]);
                ldsm4t(sb + SM_BLO + boff, bl[0], bl[1], bl[2], bl[3]);
#pragma unroll
                for (int mt = 0; mt < 2; ++mt) {
                    mma16816(acc[mt][nt2 * 2],     ah[mt], bh[0], bh[1]);
                    mma16816(acc[mt][nt2 * 2],     ah[mt], bl[0], bl[1]);
                    mma16816(acc[mt][nt2 * 2],     al[mt], bh[0], bh[1]);
                    mma16816(acc[mt][nt2 * 2 + 1], ah[mt], bh[2], bh[3]);
                    mma16816(acc[mt][nt2 * 2 + 1], ah[mt], bl[2], bl[3]);
                    mma16816(acc[mt][nt2 * 2 + 1], al[mt], bh[2], bh[3]);
                }
            }
        }
        __syncthreads();

        // ---- epilogue: pooled select by sign(g1) + sums ----
#pragma unroll
        for (int h = 0; h < 2; ++h) {
            if (nwarp == h) {
#pragma unroll
                for (int mt = 0; mt < 2; ++mt)
#pragma unroll
                    for (int nt = 0; nt < 16; ++nt) {
                        int row = m0 + mt * 16 + g8;
                        int col = nt * 8 + tig * 2;
                        float2 lo2; lo2.x = acc[mt][nt][0]; lo2.y = acc[mt][nt][1];
                        float2 hi2; hi2.x = acc[mt][nt][2]; hi2.y = acc[mt][nt][3];
                        *(float2*)(zbuf + row * ZSTRIDE + col) = lo2;
                        *(float2*)(zbuf + (row + 8) * ZSTRIDE + col) = hi2;
                    }
            }
            __syncthreads();
            for (int task = tid; task < 640; task += 256) {
                const int grp = task >> 7;
                const int col = task & 127;
                const float* zb = zbuf + grp * 25 * ZSTRIDE + col;
                float mx = -3.4e38f, mn = 3.4e38f, s = 0.f, q = 0.f;
#pragma unroll
                for (int r = 0; r < 25; ++r) {
                    float v = zb[r * ZSTRIDE];
                    mx = fmaxf(mx, v);
                    mn = fminf(mn, v);
                    s += v;
                    q = fmaf(v, v, q);
                }
                const size_t node = (size_t)(5 * gt + grp);
                const float g1v = __ldg(&g1[h * 128 + col]);
                d_poolZ[node * TT + h * 128 + col] = (g1v >= 0.f) ? mx : mn;
                sAcc[h] += s;
                qAcc[h] += q;
            }
            __syncthreads();
        }
    }

    {
        const int b = tid >> 7, col = tid & 127;
#pragma unroll
        for (int h = 0; h < 2; ++h) {
            d_pBs2[blockIdx.x * 512 + b * 256 + h * 128 + col] = sAcc[h];
            d_pBq2[blockIdx.x * 512 + b * 256 + h * 128 + col] = qAcc[h];
        }
    }
}

// ---------------- stats1: one block per column, tree reduce (deterministic) ----------------
__global__ void __launch_bounds__(128, 1)
stats1(const float* __restrict__ g1, const float* __restrict__ b1) {
    __shared__ double ss[128], qq[128];
    const int c = blockIdx.x;     // 0..255
    const int t = threadIdx.x;    // 0..127
    double s = 0.0, q = 0.0;
    for (int i = t; i < NBLK * 2; i += 128) {
        s += (double)d_pBs2[i * 256 + c];
        q += (double)d_pBq2[i * 256 + c];
    }
    ss[t] = s; qq[t] = q;
    __syncthreads();
#pragma unroll
    for (int w = 64; w >= 1; w >>= 1) {
        if (t < w) { ss[t] += ss[t + w]; qq[t] += qq[t + w]; }
        __syncthreads();
    }
    if (t == 0) {
        const double inv = 1.0 / (double)NKTOT;
        const double m = ss[0] * inv;
        const double var = qq[0] * inv - m * m;
        const float a = g1[c] * rsqrtf((float)var + EPSB);
        d_a1[c] = a;
        d_c1[c] = b1[c] - a * (float)m;
    }
}

// ---------------- merged pass C1+C2 (grid 2*NBLK) ----------------
__global__ void __launch_bounds__(256, 1)
passC12(const float* __restrict__ selfn, const float* __restrict__ Ws,
        const float* __restrict__ Wn) {
    __shared__ float sm[4096];
    const int tid = threadIdx.x;
    const int grp = tid >> 7;
    const int j = tid & 127;

    if (blockIdx.x < NBLK) {
        // ===== C1: SW = self @ Ws, 8 nodes per barrier pair =====
        const int bid = blockIdx.x;
        u64 w2[64];
#pragma unroll
        for (int i = 0; i < 64; ++i)
            w2[i] = pack2(Ws[(2 * i) * OUTD + j], Ws[(2 * i + 1) * OUTD + j]);

        float s = 0.f, q = 0.f;
        for (int base = bid * 8; base < NN; base += NBLK * 8) {
            __syncthreads();
#pragma unroll
            for (int k = 0; k < 4; ++k)
                sm[tid + k * 256] = selfn[(size_t)base * FF + tid + k * 256];
            __syncthreads();
#pragma unroll
            for (int nd = 0; nd < 4; ++nd) {
                const ulonglong2* xr = (const ulonglong2*)(sm + (grp * 4 + nd) * FF);
                u64 a0 = 0ull, a1 = 0ull;
#pragma unroll
                for (int i = 0; i < 32; ++i) {
                    ulonglong2 xv = xr[i];
                    fma2(a0, xv.x, w2[2 * i]);
                    fma2(a1, xv.y, w2[2 * i + 1]);
                }
                float2 fa = unpack2(a0), fb = unpack2(a1);
                float z = (fa.x + fa.y) + (fb.x + fb.y);
                d_SW[(size_t)(base + grp * 4 + nd) * OUTD + j] = z;
                s += z;
                q = fmaf(z, z, q);
            }
        }
        d_pC1s[bid * 256 + tid] = s;
        d_pC1q[bid * 256 + tid] = q;
    } else {
        // ===== C2: PW = (a1*poolZ + c1) @ Wn, affine folded into weights =====
        const int bid = blockIdx.x - NBLK;
        float* pos = sm;
        float* sred = sm + 2048;
        u64 w2[64];
        float cst = 0.f;
#pragma unroll
        for (int i = 0; i < 64; ++i) {
            const int t0 = grp * 128 + 2 * i;
            const float wa = Wn[t0 * OUTD + j];
            const float wb = Wn[(t0 + 1) * OUTD + j];
            w2[i] = pack2(d_a1[t0] * wa, d_a1[t0 + 1] * wb);
            cst += d_c1[t0] * wa + d_c1[t0 + 1] * wb;
        }

        float s = 0.f, q = 0.f;
        for (int base = bid * 8; base < NN; base += NBLK * 8) {
            __syncthreads();
#pragma unroll
            for (int k = 0; k < 8; ++k)
                pos[k * 256 + tid] = d_poolZ[(size_t)(base + k) * TT + tid];
            __syncthreads();
#pragma unroll
            for (int nd = 0; nd < 8; ++nd) {
                const ulonglong2* xr = (const ulonglong2*)(pos + nd * TT + grp * 128);
                u64 a0 = 0ull, a1v = 0ull;
#pragma unroll
                for (int i = 0; i < 32; ++i) {
                    ulonglong2 xv = xr[i];
                    fma2(a0, xv.x, w2[2 * i]);
                    fma2(a1v, xv.y, w2[2 * i + 1]);
                }
                float2 fa = unpack2(a0), fb = unpack2(a1v);
                sred[grp * 1024 + nd * 128 + j] = (fa.x + fa.y) + (fb.x + fb.y) + cst;
            }
            __syncthreads();
#pragma unroll
            for (int k = 0; k < 4; ++k) {
                const int o = tid + k * 256;
                const int nd = o >> 7;
                const float v = sred[nd * 128 + j] + sred[1024 + nd * 128 + j];
                d_PW[(size_t)(base + nd) * OUTD + j] = v;
                s += v;
                q = fmaf(v, v, q);
            }
        }
        d_pC2s[bid * 256 + tid] = s;
        d_pC2q[bid * 256 + tid] = q;
    }
}

// ---------------- stats2: one block per concat-column, tree reduce ----------------
__global__ void __launch_bounds__(128, 1)
stats2(const float* __restrict__ g2, const float* __restrict__ b2) {
    __shared__ double ss[128], qq[128];
    const int c = blockIdx.x;     // 0..255
    const int t = threadIdx.x;
    double s = 0.0, q = 0.0;
    if (c < 128) {
        for (int i = t; i < NBLK * 2; i += 128) {
            const int b = i >> 1, off = (i & 1) * 128;
            s += (double)d_pC1s[b * 256 + off + c];
            q += (double)d_pC1q[b * 256 + off + c];
        }
    } else {
        const int jr = c - 128;
        for (int i = t; i < NBLK * 2; i += 128) {
            const int b = i >> 1, off = (i & 1) * 128;
            s += (double)d_pC2s[b * 256 + off + jr];
            q += (double)d_pC2q[b * 256 + off + jr];
        }
    }
    ss[t] = s; qq[t] = q;
    __syncthreads();
#pragma unroll
    for (int w = 64; w >= 1; w >>= 1) {
        if (t < w) { ss[t] += ss[t + w]; qq[t] += qq[t + w]; }
        __syncthreads();
    }
    if (t == 0) {
        const double inv = 1.0 / (double)NN;
        const double m = ss[0] * inv;
        const double var = qq[0] * inv - m * m;
        const float a = g2[c] * rsqrtf((float)var + EPSB);
        d_a2[c] = a;
        d_c2[c] = b2[c] - a * (float)m;
    }
}

// ---------------- pass E: 4 float4 per thread ----------------
__global__ void passE(float* __restrict__ out) {
    const int base = (blockIdx.x * blockDim.x + threadIdx.x) * 4;
#pragma unroll
    for (int u = 0; u < 4; ++u) {
        const int idx = base + u;
        if (idx >= NN * 64) return;
        const int n = idx >> 6;
        const int c4 = idx & 63;
        float4 v;
        if (c4 < 32) v = ((const float4*)d_SW)[(size_t)n * 32 + c4];
        else         v = ((const float4*)d_PW)[(size_t)n * 32 + (c4 - 32)];
        const float4 a = ((const float4*)d_a2)[c4];
        const float4 c = ((const float4*)d_c2)[c4];
        float4 r;
        r.x = fmaxf(0.f, fmaf(a.x, v.x, c.x));
        r.y = fmaxf(0.f, fmaf(a.y, v.y, c.y));
        r.z = fmaxf(0.f, fmaf(a.z, v.z, c.z));
        r.w = fmaxf(0.f, fmaf(a.w, v.w, c.w));
        ((float4*)out)[idx] = r;
    }
}

// ---------------- launch ----------------
extern "C" void kernel_launch(void* const* d_in, const int* in_sizes, int n_in,
                              void* d_out, int out_size) {
    const float* selfn = (const float*)d_in[0];
    const float* neigh = (const float*)d_in[1];
    const float* Wt = (const float*)d_in[3];
    const float* g1 = (const float*)d_in[5];
    const float* b1 = (const float*)d_in[6];
    const float* Wn = (const float*)d_in[7];
    const float* Ws = (const float*)d_in[8];
    const float* g2 = (const float*)d_in[9];
    const float* b2 = (const float*)d_in[10];
    float* out = (float*)d_out;

    static int configured = 0;
    if (!configured) {
        cudaFuncSetAttribute(passB, cudaFuncAttributeMaxDynamicSharedMemorySize, SM_TOTAL);
        configured = 1;
    }

    passB<<<NBLK, 256, SM_TOTAL>>>(neigh, Wt, g1);
    stats1<<<256, 128>>>(g1, b1);
    passC12<<<2 * NBLK, 256>>>(selfn, Ws, Wn);
    stats2<<<256, 128>>>(g2, b2);
    passE<<<(NN * 64 + 1023) / 1024, 256>>>(out);
}